// round 2
// baseline (speedup 1.0000x reference)
#include <cuda_runtime.h>
#include <cuda_bf16.h>

// SimpleRNN: h_t = tanh(a*x_t + b*h_{t-1} + c), output h_T per row.
//
// R2 changes vs R1:
//  1. Software-pipelined prefetch: next 16 x-values loaded into registers
//     before the serial chain consumes the current 16 -> hides L2/DRAM latency
//     (chain per batch 320cyc >= L2 latency ~250cyc).
//  2. Hybrid precision: tanh.approx.f32 (20 cyc/step chain) for all but the
//     last K_p steps; exact ex2/rcp formulation (40 cyc/step) for the tail.
//     Errors injected >= K_p steps before the end are damped by |b|^K_p:
//     K_p = ceil(ln(100/(1-|b|)) / (-ln|b|)) bounds the approx-phase
//     contribution to ~1e-5 << 1e-3 tolerance. As |b|->1, K_p->K (all exact).
//  3. Truncation horizon K = ceil(18.5 / -ln|b|) as before (|b|^K ~ 9e-9).

#define RNN_T 4096
#define AB 16   // approx-phase batch (16*20 = 320 cyc chain per batch)
#define PB 8    // precise-phase batch (8*40 = 320 cyc chain per batch)

__device__ __forceinline__ float ex2_approx(float x) {
    float y; asm("ex2.approx.f32 %0, %1;" : "=f"(y) : "f"(x)); return y;
}
__device__ __forceinline__ float rcp_approx(float x) {
    float y; asm("rcp.approx.f32 %0, %1;" : "=f"(y) : "f"(x)); return y;
}
__device__ __forceinline__ float tanh_approx(float x) {
    float y; asm("tanh.approx.f32 %0, %1;" : "=f"(y) : "f"(x)); return y;
}

__global__ void __launch_bounds__(128)
simple_rnn_kernel(const float* __restrict__ x,
                  const float* __restrict__ w_ih,
                  const float* __restrict__ w_hh,
                  const float* __restrict__ b_ih,
                  const float* __restrict__ b_hh,
                  float* __restrict__ out,
                  int B) {
    int r = blockIdx.x * blockDim.x + threadIdx.x;
    if (r >= B) return;

    const float a = w_ih[0];
    const float b = w_hh[0];
    const float c = b_ih[0] + b_hh[0];

    // ---- truncation horizon K and precise-tail length Kp ----
    float ab = fabsf(b);
    float l  = __logf(ab);               // < 0 for |b| < 1
    int K, Kp;
    if (!(l < -1e-9f)) {                 // |b| >= 1 or degenerate: all exact
        K = RNN_T; Kp = RNN_T;
    } else {
        float inv = 1.0f / (-l);
        float kf = 18.5f * inv;          // |b|^K <= e^-18.5
        K = (kf >= (float)RNN_T) ? RNN_T : (int)kf + 1;
        // approx-phase error <= eps * |b|^Kp / (1-|b|) <= eps/100 ~ 1e-5
        float kp = __logf(100.0f / (1.0f - ab)) * inv;
        Kp = (kp >= (float)K) ? K : (int)kp + 1;
    }
    if (K  < 1) K  = 1;
    if (Kp < 1) Kp = 1;
    if (Kp > K) Kp = K;
    int Ka = K - Kp;                     // approx steps first

    const float* __restrict__ xr = x + (size_t)r * RNN_T + (RNN_T - K);

    float h = 0.0f;
    int t = 0;

    // ================= approx phase: h = tanh.approx(b*h + w) =================
    if (Ka >= AB) {
        float buf[AB];
#pragma unroll
        for (int i = 0; i < AB; i++) buf[i] = xr[i];

        for (; t + 2 * AB <= Ka; t += AB) {
            float nxt[AB];
#pragma unroll
            for (int i = 0; i < AB; i++) nxt[i] = xr[t + AB + i];  // prefetch
#pragma unroll
            for (int i = 0; i < AB; i++) {
                float w = fmaf(buf[i], a, c);                      // off-chain
                h = tanh_approx(fmaf(b, h, w));                    // 20-cyc chain
            }
#pragma unroll
            for (int i = 0; i < AB; i++) buf[i] = nxt[i];
        }
        // drain the last full batch already in buf
#pragma unroll
        for (int i = 0; i < AB; i++) {
            float w = fmaf(buf[i], a, c);
            h = tanh_approx(fmaf(b, h, w));
        }
        t += AB;
    }
    for (; t < Ka; t++)
        h = tanh_approx(fmaf(b, h, fmaf(xr[t], a, c)));

    // ================= exact phase: r-formulation =================
    // r = 1/(exp2(z)+1), h = 1-2r;  z' = M*r + W,  W = 2log2e*(a*x + b + c)
    const float L2 = 2.0f * 1.4426950408889634f;
    const float A2 = L2 * a;
    const float C2 = L2 * (b + c);
    const float M  = -2.0f * L2 * b;

    float rr = fmaf(-0.5f, h, 0.5f);     // h -> r

    if (K - t >= PB) {
        float buf[PB];
#pragma unroll
        for (int i = 0; i < PB; i++) buf[i] = xr[t + i];

        for (; t + 2 * PB <= K; t += PB) {
            float nxt[PB];
#pragma unroll
            for (int i = 0; i < PB; i++) nxt[i] = xr[t + PB + i];  // prefetch
#pragma unroll
            for (int i = 0; i < PB; i++) {
                float w = fmaf(buf[i], A2, C2);                    // off-chain
                float z = fmaf(M, rr, w);                          // 40-cyc chain
                rr = rcp_approx(ex2_approx(z) + 1.0f);
            }
#pragma unroll
            for (int i = 0; i < PB; i++) buf[i] = nxt[i];
        }
#pragma unroll
        for (int i = 0; i < PB; i++) {
            float w = fmaf(buf[i], A2, C2);
            float z = fmaf(M, rr, w);
            rr = rcp_approx(ex2_approx(z) + 1.0f);
        }
        t += PB;
    }
    for (; t < K; t++) {
        float w = fmaf(xr[t], A2, C2);
        float z = fmaf(M, rr, w);
        rr = rcp_approx(ex2_approx(z) + 1.0f);
    }

    out[r] = fmaf(-2.0f, rr, 1.0f);      // h_T = 1 - 2*r
}

extern "C" void kernel_launch(void* const* d_in, const int* in_sizes, int n_in,
                              void* d_out, int out_size) {
    const float* x    = (const float*)d_in[0];
    const float* w_ih = (const float*)d_in[1];
    const float* w_hh = (const float*)d_in[2];
    const float* b_ih = (const float*)d_in[3];
    const float* b_hh = (const float*)d_in[4];
    float* out = (float*)d_out;

    int B = out_size;                 // output is [B, 1] float32
    int threads = 128;
    int blocks = (B + threads - 1) / threads;
    simple_rnn_kernel<<<blocks, threads>>>(x, w_ih, w_hh, b_ih, b_hh, out, B);
}

// round 3
// speedup vs baseline: 1.4624x; 1.4624x over previous
#include <cuda_runtime.h>
#include <cuda_bf16.h>

// SimpleRNN: h_t = tanh(a*x_t + b*h_{t-1} + c), output h_T per row (B=8192, T=4096).
//
// R3: cut total cycles by construction (kernel runs at DVFS-floor clock; only
// absolute cycle count matters):
//  1. Truncation: |b|^K <= 1e-5  ->  K = 11.51/(-ln|b|)   (~45 steps vs 72).
//     Truncation abs error <= |b|^K = 1e-5 << 1e-3 gate.
//  2. MUFU.TANH chain (FFMA+TANH = 20 cyc/step) for all but the last Kt steps;
//     exact ex2/rcp tail (40 cyc/step). Kt sized so tanh.approx error (<=5e-4)
//     damped below 1e-4: |b|^Kt <= 0.2*(1-|b|) -> Kt = ln(5/(1-|b|))/(-ln|b|).
//     As |b|->1 both K and Kt saturate at T (falls back to exact full scan).
//  3. 32-thread blocks -> 256 CTAs over all 148 SMs (was 64 CTAs / 64 SMs).

#define RNN_T 4096

__device__ __forceinline__ float ex2_approx(float x) {
    float y; asm("ex2.approx.f32 %0, %1;" : "=f"(y) : "f"(x)); return y;
}
__device__ __forceinline__ float rcp_approx(float x) {
    float y; asm("rcp.approx.f32 %0, %1;" : "=f"(y) : "f"(x)); return y;
}
__device__ __forceinline__ float tanh_approx(float x) {
    float y; asm("tanh.approx.f32 %0, %1;" : "=f"(y) : "f"(x)); return y;
}

__global__ void __launch_bounds__(32)
simple_rnn_kernel(const float* __restrict__ x,
                  const float* __restrict__ w_ih,
                  const float* __restrict__ w_hh,
                  const float* __restrict__ b_ih,
                  const float* __restrict__ b_hh,
                  float* __restrict__ out,
                  int B) {
    int r = blockIdx.x * blockDim.x + threadIdx.x;
    if (r >= B) return;

    const float a = w_ih[0];
    const float b = w_hh[0];
    const float c = b_ih[0] + b_hh[0];

    // ---- horizons ----
    float ab = fabsf(b);
    float l  = __logf(ab);                 // < 0 for |b| < 1 (-inf for b==0)
    int K, Kt;
    if (!(l < -1e-9f)) {                   // |b| >= 1 / degenerate: full exact
        K = RNN_T; Kt = RNN_T;
    } else {
        float inv = 1.0f / (-l);
        float kf = 11.513f * inv;          // |b|^K <= 1e-5
        K = (kf >= (float)RNN_T) ? RNN_T : (int)kf + 1;
        float kt = __logf(5.0f / (1.0f - ab)) * inv;   // damp tanh.approx err
        Kt = (kt >= (float)K) ? K : (int)kt + 1;
    }
    if (K  < 1) K  = 1;
    if (Kt < 1) Kt = 1;
    if (Kt > K) Kt = K;
    const int Ka = K - Kt;                 // approx steps first

    const float* __restrict__ xr = x + (size_t)r * RNN_T + (RNN_T - K);

    float h = 0.0f;

    // ---- approx phase: h = tanh.approx(b*h + (a*x + c)), 20 cyc/step ----
    int t = 0;
#pragma unroll 16
    for (; t < Ka; t++) {
        float w = fmaf(xr[t], a, c);       // off the serial chain
        h = tanh_approx(fmaf(b, h, w));
    }

    // ---- exact tail: r = 1/(exp2(z)+1), h = 1-2r ----
    const float L2 = 2.0f * 1.4426950408889634f;   // 2*log2(e)
    const float A2 = L2 * a;
    const float C2 = L2 * (b + c);
    const float M  = -2.0f * L2 * b;

    float rr = fmaf(-0.5f, h, 0.5f);
#pragma unroll 8
    for (; t < K; t++) {
        float w = fmaf(xr[t], A2, C2);     // off the serial chain
        float z = fmaf(M, rr, w);
        rr = rcp_approx(ex2_approx(z) + 1.0f);
    }

    out[r] = fmaf(-2.0f, rr, 1.0f);        // h_T = 1 - 2*r
}

extern "C" void kernel_launch(void* const* d_in, const int* in_sizes, int n_in,
                              void* d_out, int out_size) {
    const float* x    = (const float*)d_in[0];
    const float* w_ih = (const float*)d_in[1];
    const float* w_hh = (const float*)d_in[2];
    const float* b_ih = (const float*)d_in[3];
    const float* b_hh = (const float*)d_in[4];
    float* out = (float*)d_out;

    int B = out_size;                  // output is [B, 1] float32
    int threads = 32;                  // 1 warp/CTA -> 256 CTAs over 148 SMs
    int blocks = (B + threads - 1) / threads;
    simple_rnn_kernel<<<blocks, threads>>>(x, w_ih, w_hh, b_ih, b_hh, out, B);
}

// round 4
// speedup vs baseline: 1.5055x; 1.0295x over previous
#include <cuda_runtime.h>
#include <cuda_bf16.h>

// SimpleRNN: h_t = tanh(a*x_t + b*h_{t-1} + c), output h_T per row (B=8192, T=4096).
//
// R3: cut total cycles by construction (kernel runs at DVFS-floor clock; only
// absolute cycle count matters):
//  1. Truncation: |b|^K <= 1e-5  ->  K = 11.51/(-ln|b|)   (~45 steps vs 72).
//     Truncation abs error <= |b|^K = 1e-5 << 1e-3 gate.
//  2. MUFU.TANH chain (FFMA+TANH = 20 cyc/step) for all but the last Kt steps;
//     exact ex2/rcp tail (40 cyc/step). Kt sized so tanh.approx error (<=5e-4)
//     damped below 1e-4: |b|^Kt <= 0.2*(1-|b|) -> Kt = ln(5/(1-|b|))/(-ln|b|).
//     As |b|->1 both K and Kt saturate at T (falls back to exact full scan).
//  3. 32-thread blocks -> 256 CTAs over all 148 SMs (was 64 CTAs / 64 SMs).

#define RNN_T 4096

__device__ __forceinline__ float ex2_approx(float x) {
    float y; asm("ex2.approx.f32 %0, %1;" : "=f"(y) : "f"(x)); return y;
}
__device__ __forceinline__ float rcp_approx(float x) {
    float y; asm("rcp.approx.f32 %0, %1;" : "=f"(y) : "f"(x)); return y;
}
__device__ __forceinline__ float tanh_approx(float x) {
    float y; asm("tanh.approx.f32 %0, %1;" : "=f"(y) : "f"(x)); return y;
}

__global__ void __launch_bounds__(32)
simple_rnn_kernel(const float* __restrict__ x,
                  const float* __restrict__ w_ih,
                  const float* __restrict__ w_hh,
                  const float* __restrict__ b_ih,
                  const float* __restrict__ b_hh,
                  float* __restrict__ out,
                  int B) {
    int r = blockIdx.x * blockDim.x + threadIdx.x;
    if (r >= B) return;

    const float a = w_ih[0];
    const float b = w_hh[0];
    const float c = b_ih[0] + b_hh[0];

    // ---- horizons ----
    float ab = fabsf(b);
    float l  = __logf(ab);                 // < 0 for |b| < 1 (-inf for b==0)
    int K, Kt;
    if (!(l < -1e-9f)) {                   // |b| >= 1 / degenerate: full exact
        K = RNN_T; Kt = RNN_T;
    } else {
        float inv = 1.0f / (-l);
        float kf = 11.513f * inv;          // |b|^K <= 1e-5
        K = (kf >= (float)RNN_T) ? RNN_T : (int)kf + 1;
        float kt = __logf(5.0f / (1.0f - ab)) * inv;   // damp tanh.approx err
        Kt = (kt >= (float)K) ? K : (int)kt + 1;
    }
    if (K  < 1) K  = 1;
    if (Kt < 1) Kt = 1;
    if (Kt > K) Kt = K;
    const int Ka = K - Kt;                 // approx steps first

    const float* __restrict__ xr = x + (size_t)r * RNN_T + (RNN_T - K);

    float h = 0.0f;

    // ---- approx phase: h = tanh.approx(b*h + (a*x + c)), 20 cyc/step ----
    int t = 0;
#pragma unroll 16
    for (; t < Ka; t++) {
        float w = fmaf(xr[t], a, c);       // off the serial chain
        h = tanh_approx(fmaf(b, h, w));
    }

    // ---- exact tail: r = 1/(exp2(z)+1), h = 1-2r ----
    const float L2 = 2.0f * 1.4426950408889634f;   // 2*log2(e)
    const float A2 = L2 * a;
    const float C2 = L2 * (b + c);
    const float M  = -2.0f * L2 * b;

    float rr = fmaf(-0.5f, h, 0.5f);
#pragma unroll 8
    for (; t < K; t++) {
        float w = fmaf(xr[t], A2, C2);     // off the serial chain
        float z = fmaf(M, rr, w);
        rr = rcp_approx(ex2_approx(z) + 1.0f);
    }

    out[r] = fmaf(-2.0f, rr, 1.0f);        // h_T = 1 - 2*r
}

extern "C" void kernel_launch(void* const* d_in, const int* in_sizes, int n_in,
                              void* d_out, int out_size) {
    const float* x    = (const float*)d_in[0];
    const float* w_ih = (const float*)d_in[1];
    const float* w_hh = (const float*)d_in[2];
    const float* b_ih = (const float*)d_in[3];
    const float* b_hh = (const float*)d_in[4];
    float* out = (float*)d_out;

    int B = out_size;                  // output is [B, 1] float32
    int threads = 32;                  // 1 warp/CTA -> 256 CTAs over 148 SMs
    int blocks = (B + threads - 1) / threads;
    simple_rnn_kernel<<<blocks, threads>>>(x, w_ih, w_hh, b_ih, b_hh, out, B);
}